// round 16
// baseline (speedup 1.0000x reference)
#include <cuda_runtime.h>
#include <cuda_fp16.h>
#include <math.h>
#include <stdint.h>

#define NH   16
#define HD   64
#define NB   2
#define SEQ  2048
#define DM   1024
#define MTOT (NB*SEQ)

// ---------------- device scratch (allocation-free rule) ----------------
__device__ __align__(256) __half g_Qh[(size_t)NB*NH*SEQ*HD];
__device__ __align__(256) __half g_Kh[(size_t)NB*NH*SEQ*HD];
__device__ __align__(256) __half g_Vh[(size_t)NB*NH*SEQ*HD];
__device__ __align__(256) __half g_xh[(size_t)MTOT*DM];
__device__ __align__(256) __half g_ch[(size_t)MTOT*DM];
__device__ __align__(256) __half g_w4[4][(size_t)DM*DM];   // Wq,Wk,Wv,Wo fp16

// ---------------- helpers ----------------
__device__ __forceinline__ uint32_t smem_u32(const void* p) {
    uint32_t a;
    asm("{ .reg .u64 t; cvta.to.shared.u64 t, %1; cvt.u32.u64 %0, t; }" : "=r"(a) : "l"(p));
    return a;
}
__device__ __forceinline__ uint32_t sw128(uint32_t o) {   // 128B rows
    return o ^ (((o >> 7) & 7u) << 4);
}
__device__ __forceinline__ uint32_t sw64(uint32_t o) {    // 64B rows
    return o ^ (((o >> 7) & 3u) << 4);
}
__device__ __forceinline__ void cpasync16(uint32_t dst, const void* src) {
    asm volatile("cp.async.cg.shared.global [%0], [%1], 16;" :: "r"(dst), "l"(src));
}
__device__ __forceinline__ void cp_commit() {
    asm volatile("cp.async.commit_group;" ::: "memory");
}
__device__ __forceinline__ void cp_wait1() {
    asm volatile("cp.async.wait_group 1;" ::: "memory");
}
__device__ __forceinline__ void cp_wait2() {
    asm volatile("cp.async.wait_group 2;" ::: "memory");
}
__device__ __forceinline__ void cp_wait0() {
    asm volatile("cp.async.wait_group 0;" ::: "memory");
}
__device__ __forceinline__ void ldsm_x4(uint32_t a, uint32_t* r) {
    asm volatile("ldmatrix.sync.aligned.m8n8.x4.shared.b16 {%0,%1,%2,%3}, [%4];"
                 : "=r"(r[0]), "=r"(r[1]), "=r"(r[2]), "=r"(r[3]) : "r"(a));
}
__device__ __forceinline__ void ldsm_x4t(uint32_t a, uint32_t* r) {
    asm volatile("ldmatrix.sync.aligned.m8n8.x4.trans.shared.b16 {%0,%1,%2,%3}, [%4];"
                 : "=r"(r[0]), "=r"(r[1]), "=r"(r[2]), "=r"(r[3]) : "r"(a));
}
__device__ __forceinline__ void mma16816(float* c, const uint32_t* a,
                                         uint32_t b0, uint32_t b1) {
    asm volatile(
        "mma.sync.aligned.m16n8k16.row.col.f32.f16.f16.f32 "
        "{%0,%1,%2,%3}, {%4,%5,%6,%7}, {%8,%9}, {%0,%1,%2,%3};"
        : "+f"(c[0]), "+f"(c[1]), "+f"(c[2]), "+f"(c[3])
        : "r"(a[0]), "r"(a[1]), "r"(a[2]), "r"(a[3]), "r"(b0), "r"(b1));
}
__device__ __forceinline__ float ex2f(float e) {
    float r;
    asm("ex2.approx.f32 %0, %1;" : "=f"(r) : "f"(e));
    return r;
}
__device__ __forceinline__ uint32_t packh(float lo, float hi) {
    __half2 h = __floats2half2_rn(lo, hi);
    return *(uint32_t*)&h;
}

// ---------------- conversions fp32 -> fp16 (x + 4 weights, one launch) ----
#define XB ((int)((size_t)MTOT * DM / 4 / 256))   // 4096
#define WB ((int)((size_t)DM * DM / 4 / 256))     // 1024
__global__ __launch_bounds__(256) void conv_all(const float4* __restrict__ x,
                                                const float4* __restrict__ w0,
                                                const float4* __restrict__ w1,
                                                const float4* __restrict__ w2,
                                                const float4* __restrict__ w3) {
    int blk = blockIdx.x;
    const float4* src;
    __half2* dst;
    int i;
    if (blk < XB) {
        src = x; dst = (__half2*)g_xh;
        i = blk * 256 + threadIdx.x;
    } else {
        blk -= XB;
        const int s = blk / WB;
        src = (s == 0) ? w0 : (s == 1) ? w1 : (s == 2) ? w2 : w3;
        dst = (__half2*)g_w4[s];
        i = (blk - s * WB) * 256 + threadIdx.x;
    }
    float4 v = src[i];
    dst[2*i]   = __floats2half2_rn(v.x, v.y);
    dst[2*i+1] = __floats2half2_rn(v.z, v.w);
}

// ---------------- shared GEMM mainloop (CTA 128x128, BK=32, 3-stage) ------
#define GSTG 16384   // stage stride: A 8K + B 8K

struct GemmCore {
    uint32_t sb;
    int tid, wid, lid, wm, wn, bm, bn;
    float acc[2][8][4];

    __device__ __forceinline__ void init(uint32_t sb_, int bm_, int bn_) {
        sb = sb_; tid = threadIdx.x; wid = tid >> 5; lid = tid & 31;
        wm = wid & 3; wn = wid >> 2; bm = bm_; bn = bn_;
        #pragma unroll
        for (int mi = 0; mi < 2; mi++)
            #pragma unroll
            for (int ni = 0; ni < 8; ni++)
                #pragma unroll
                for (int e = 0; e < 4; e++) acc[mi][ni][e] = 0.f;
    }
    __device__ __forceinline__ void load_stage(const __half* A_, const __half* B_,
                                               int c) {
        const uint32_t base = sb + (uint32_t)(c % 3) * GSTG;
        #pragma unroll
        for (int p = 0; p < 2; p++) {
            const int id = tid + p * 256;
            const int row = id >> 2, ch = id & 3;
            const uint32_t so = sw64((uint32_t)(row * 64 + ch * 16));
            const size_t ga = (size_t)(bm + row) * (DM / 8) + c * 4 + ch;
            const size_t gb = (size_t)(bn + row) * (DM / 8) + c * 4 + ch;
            cpasync16(base + so,        (const uint4*)A_ + ga);
            cpasync16(base + 8192 + so, (const uint4*)B_ + gb);
        }
        cp_commit();
    }
    __device__ __forceinline__ void mainloop(const __half* A_, const __half* B_) {
        const int NIT = DM / 32;
        load_stage(A_, B_, 0);
        load_stage(A_, B_, 1);
        for (int c = 0; c < NIT; c++) {
            if (c == NIT - 1) cp_wait0(); else cp_wait1();
            __syncthreads();
            const uint32_t base = sb + (uint32_t)(c % 3) * GSTG;
            #pragma unroll
            for (int ks = 0; ks < 2; ks++) {
                uint32_t ah[2][4];
                #pragma unroll
                for (int mi = 0; mi < 2; mi++) {
                    const int row = wm * 32 + mi * 16 + (lid & 15);
                    const int colb = (ks * 16 + (lid >> 4) * 8) * 2;
                    ldsm_x4(base + sw64((uint32_t)(row * 64 + colb)), ah[mi]);
                }
                uint32_t bh[8][2];
                #pragma unroll
                for (int nj = 0; nj < 4; nj++) {
                    const int row = wn * 64 + nj * 16 + ((lid >> 4) << 3) + (lid & 7);
                    const int colb = (ks * 16 + ((lid >> 3) & 1) * 8) * 2;
                    uint32_t t[4];
                    ldsm_x4(base + 8192 + sw64((uint32_t)(row * 64 + colb)), t);
                    bh[nj*2][0] = t[0]; bh[nj*2][1] = t[1];
                    bh[nj*2+1][0] = t[2]; bh[nj*2+1][1] = t[3];
                }
                #pragma unroll
                for (int mi = 0; mi < 2; mi++)
                    #pragma unroll
                    for (int ni = 0; ni < 8; ni++)
                        mma16816(acc[mi][ni], ah[mi], bh[ni][0], bh[ni][1]);
            }
            if (c + 2 < NIT) load_stage(A_, B_, c + 2);
        }
    }
};

// QKV fused: z = 0/1/2 -> Q/K/V, half out [b,h,s,d]. Q pre-scaled.
__global__ __launch_bounds__(256, 2)
void gemm_qkv(const __half* __restrict__ A_,
              const float* __restrict__ bq, const float* __restrict__ bk,
              const float* __restrict__ bv)
{
    extern __shared__ char smb[];
    const int z = blockIdx.z;
    const __half* B_ = g_w4[z];
    const float* bias = (z == 0) ? bq : (z == 1) ? bk : bv;
    __half* OutH = (z == 0) ? g_Qh : (z == 1) ? g_Kh : g_Vh;
    const float scl = (z == 0) ? 0.180336880111f : 1.0f;   // 0.125 * log2(e)

    GemmCore g;
    g.init(smem_u32(smb), blockIdx.y * 128, blockIdx.x * 128);
    g.mainloop(A_, B_);

    const int qr = g.lid >> 2, qc = g.lid & 3;
    #pragma unroll
    for (int mi = 0; mi < 2; mi++) {
        #pragma unroll
        for (int half = 0; half < 2; half++) {
            const int m = g.bm + g.wm * 32 + mi * 16 + half * 8 + qr;
            const int n0 = g.bn + g.wn * 64;
            const int b = m >> 11, s = m & (SEQ - 1);
            const int h = n0 >> 6;
            const size_t base = ((size_t)(b * NH + h) * SEQ + s) * HD;
            #pragma unroll
            for (int ni = 0; ni < 8; ni++) {
                const int nloc = ni * 8 + qc * 2;
                const int ng = n0 + nloc;
                *(__half2*)(OutH + base + nloc) = __floats2half2_rn(
                    (g.acc[mi][ni][half*2+0] + bias[ng]) * scl,
                    (g.acc[mi][ni][half*2+1] + bias[ng + 1]) * scl);
            }
        }
    }
}

// Output GEMM: fp32 row-major into d_out  (clock canary: ~29 us at full clock)
__global__ __launch_bounds__(256, 2)
void gemm_o(const __half* __restrict__ A_, const float* __restrict__ bias,
            float* __restrict__ Out)
{
    extern __shared__ char smb[];
    GemmCore g;
    g.init(smem_u32(smb), blockIdx.y * 128, blockIdx.x * 128);
    g.mainloop(A_, g_w4[3]);

    const int qr = g.lid >> 2, qc = g.lid & 3;
    #pragma unroll
    for (int mi = 0; mi < 2; mi++) {
        #pragma unroll
        for (int half = 0; half < 2; half++) {
            const int m = g.bm + g.wm * 32 + mi * 16 + half * 8 + qr;
            const int n0 = g.bn + g.wn * 64;
            float* dst = Out + (size_t)m * DM;
            #pragma unroll
            for (int ni = 0; ni < 8; ni++) {
                const int ng = n0 + ni * 8 + qc * 2;
                float2 o;
                o.x = g.acc[mi][ni][half*2+0] + bias[ng];
                o.y = g.acc[mi][ni][half*2+1] + bias[ng + 1];
                *(float2*)(dst + ng) = o;
            }
        }
    }
}

// ---------------- fp16 tensor-core flash attention (deep split-commit) ----
// grid (SEQ/128, NB*NH), 256 threads, 2 CTAs/SM. Q in regs (pre-scaled).
// Per tile TWO cp.async groups: [K 8K] and [V 8K + mask 34K], BOTH for kt+1
// issued at top of iter kt (right after K(kt) wait) -> VM gets a full extra
// S-block of prefetch distance. FIFO: top wait<=1 -> K(kt); post-S wait<=2
// -> VM(kt).
#define MSTRIDE 272                       // 64 words + 16B pad
#define AMOFF   16384                     // mask offset within stage
#define ASTG    (16384 + 128*MSTRIDE)     // 51200
__global__ __launch_bounds__(256, 2) void attn_tc(const uint32_t* __restrict__ maskw)
{
    extern __shared__ char smb[];
    const uint32_t sb = smem_u32(smb);
    const int tid = threadIdx.x, w = tid >> 5, lane = tid & 31;
    const int bh = blockIdx.y, q0 = blockIdx.x * 128;
    const int r = lane >> 2, qc2 = (lane & 3) * 2;
    const int NT = SEQ / 64;
    const uint32_t ONES = 0x3C003C00u;   // half2 {1, 1}

    // ---- stage Q tile, pull fragments ----
    {
        const __half* Q = g_Qh + ((size_t)bh * SEQ + q0) * HD;
        const int row = tid >> 1, cg = (tid & 1) * 4;
        #pragma unroll
        for (int c = 0; c < 4; c++) {
            const uint32_t off = sw128((uint32_t)(row * 128 + (cg + c) * 16));
            *(uint4*)(smb + off) = ((const uint4*)(Q + row * HD))[cg + c];
        }
    }
    __syncthreads();
    uint32_t qh[4][4];
    {
        const int row = w * 16 + ((lane >> 3) & 1) * 8 + (lane & 7);
        #pragma unroll
        for (int kc = 0; kc < 4; kc++) {
            const int chunk = kc * 2 + (lane >> 4);
            ldsm_x4(sb + sw128((uint32_t)(row * 128 + chunk * 16)), qh[kc]);
        }
    }
    __syncthreads();

    float ctx[8][4];
    #pragma unroll
    for (int j = 0; j < 8; j++)
        #pragma unroll
        for (int e = 0; e < 4; e++) ctx[j][e] = 0.f;
    float lacc[4] = {0.f, 0.f, 0.f, 0.f};   // row sums via ones-MMA

    const __half* Kp = g_Kh + (size_t)bh * SEQ * HD;
    const __half* Vp = g_Vh + (size_t)bh * SEQ * HD;
    const uint32_t* Mbase = maskw + ((size_t)bh * SEQ + q0) * SEQ;

    // group 1: K tile only (8 KB); all 256 threads, 2 chunks each
    auto load_K = [&](int kt) {
        const uint32_t stg = sb + (uint32_t)(kt & 1) * ASTG;
        const int row = tid >> 2, cg = (tid & 3) * 2;
        const __half* src = Kp + ((size_t)(kt * 64 + row)) * HD;
        #pragma unroll
        for (int c = 0; c < 2; c++) {
            cpasync16(stg + sw128((uint32_t)(row * 128 + (cg + c) * 16)),
                      (const uint4*)src + cg + c);
        }
        cp_commit();
    };
    // group 2: V tile (8 KB) + mask slab (32 KB)
    auto load_VM = [&](int kt) {
        const uint32_t stg = sb + (uint32_t)(kt & 1) * ASTG;
        {
            const int row = tid >> 2, cg = (tid & 3) * 2;
            const __half* src = Vp + ((size_t)(kt * 64 + row)) * HD;
            #pragma unroll
            for (int c = 0; c < 2; c++) {
                cpasync16(stg + 8192 + sw128((uint32_t)(row * 128 + (cg + c) * 16)),
                          (const uint4*)src + cg + c);
            }
        }
        #pragma unroll
        for (int i = 0; i < 8; i++) {
            const int id = i * 256 + tid;
            const int row = id >> 4, ch = id & 15;
            cpasync16(stg + AMOFF + (uint32_t)(row * MSTRIDE + ch * 16),
                      Mbase + (size_t)row * SEQ + kt * 64 + ch * 4);
        }
        cp_commit();
    };

    load_K(0);
    load_VM(0);

    for (int kt = 0; kt < NT; kt++) {
        // pending at top: [K(kt), VM(kt)] -> wait<=1 releases K(kt)
        cp_wait1();
        __syncthreads();
        // issue BOTH next-tile groups now (max prefetch distance for VM)
        if (kt + 1 < NT) { load_K(kt + 1); load_VM(kt + 1); }
        const uint32_t base = sb + (uint32_t)(kt & 1) * ASTG;

        // ---- S = Q K^T (V + mask of this tile still in flight) ----
        float sacc[8][4];
        #pragma unroll
        for (int j = 0; j < 8; j++) {
            #pragma unroll
            for (int e = 0; e < 4; e++) sacc[j][e] = 0.f;
            uint32_t kb[8];
            #pragma unroll
            for (int half = 0; half < 2; half++) {
                const int row = j * 8 + (lane & 7);
                const int chunk = half * 4 + (lane >> 3);
                ldsm_x4(base + sw128((uint32_t)(row * 128 + chunk * 16)), kb + half * 4);
            }
            #pragma unroll
            for (int kc = 0; kc < 4; kc++) {
                const int i0 = (kc >> 1) * 4 + (kc & 1) * 2;
                mma16816(sacc[j], qh[kc], kb[i0], kb[i0 + 1]);
            }
        }

        // pending: [VM(kt), K(kt+1), VM(kt+1)] -> wait<=2 releases VM(kt)
        if (kt + 1 < NT) cp_wait2(); else cp_wait0();
        __syncthreads();

        // ---- mask (from smem) + exp (MUFU) + pack P ----
        uint32_t pf[4][4];
        const char* mrow0 = smb + (kt & 1) * ASTG + AMOFF + (w * 16 + r) * MSTRIDE;
        const char* mrow1 = mrow0 + 8 * MSTRIDE;
        #pragma unroll
        for (int j = 0; j < 8; j++) {
            uint2 m0 = *(const uint2*)(mrow0 + (j * 8 + qc2) * 4);
            uint2 m1 = *(const uint2*)(mrow1 + (j * 8 + qc2) * 4);
            float p0 = m0.x ? ex2f(sacc[j][0]) : 0.f;
            float p1 = m0.y ? ex2f(sacc[j][1]) : 0.f;
            float p2 = m1.x ? ex2f(sacc[j][2]) : 0.f;
            float p3 = m1.y ? ex2f(sacc[j][3]) : 0.f;
            pf[j >> 1][(j & 1) * 2 + 0] = packh(p0, p1);
            pf[j >> 1][(j & 1) * 2 + 1] = packh(p2, p3);
        }

        // ---- ctx += P V ;  lsum += P * ones ----
        #pragma unroll
        for (int kc = 0; kc < 4; kc++) {
            mma16816(lacc, pf[kc], ONES, ONES);
            #pragma unroll
            for (int dp = 0; dp < 4; dp++) {
                const int row = kc * 16 + ((lane >> 3) & 1) * 8 + (lane & 7);
                const int chunk = dp * 2 + (lane >> 4);
                uint32_t vb[4];
                ldsm_x4t(base + 8192 + sw128((uint32_t)(row * 128 + chunk * 16)), vb);
                mma16816(ctx[dp*2],   pf[kc], vb[0], vb[1]);
                mma16816(ctx[dp*2+1], pf[kc], vb[2], vb[3]);
            }
        }
    }

    // ---- normalize + write ctx (fp16) into [b, s, h*64+d] ----
    const float inv0 = (lacc[0] > 0.f) ? 1.f / lacc[0] : 0.f;
    const float inv1 = (lacc[2] > 0.f) ? 1.f / lacc[2] : 0.f;
    const int b = bh >> 4, h = bh & (NH - 1);
    const int s0 = q0 + w * 16 + r;
    const size_t base0 = ((size_t)b * SEQ + s0) * DM + h * 64;
    const size_t base1 = base0 + (size_t)8 * DM;
    #pragma unroll
    for (int j = 0; j < 8; j++) {
        const int d = j * 8 + qc2;
        *(__half2*)(g_ch + base0 + d) =
            __floats2half2_rn(ctx[j][0] * inv0, ctx[j][1] * inv0);
        *(__half2*)(g_ch + base1 + d) =
            __floats2half2_rn(ctx[j][2] * inv1, ctx[j][3] * inv1);
    }
}

// ---------------- launch ----------------
extern "C" void kernel_launch(void* const* d_in, const int* in_sizes, int n_in,
                              void* d_out, int out_size)
{
    const float* x  = (const float*)d_in[0];
    const uint32_t* maskw = (const uint32_t*)d_in[1];
    const float* Wq = (const float*)d_in[2];
    const float* bq = (const float*)d_in[3];
    const float* Wk = (const float*)d_in[4];
    const float* bk = (const float*)d_in[5];
    const float* Wv = (const float*)d_in[6];
    const float* bv = (const float*)d_in[7];
    const float* Wo = (const float*)d_in[8];
    const float* bo = (const float*)d_in[9];
    float* out = (float*)d_out;

    __half *xh, *ch;
    cudaGetSymbolAddress((void**)&xh, g_xh);
    cudaGetSymbolAddress((void**)&ch, g_ch);

    const int GEMM_SMEM = 3 * GSTG;   // 49152
    const int ATTN_SMEM = 2 * ASTG;   // 102400
    cudaFuncSetAttribute(gemm_qkv, cudaFuncAttributeMaxDynamicSharedMemorySize, GEMM_SMEM);
    cudaFuncSetAttribute(gemm_o,   cudaFuncAttributeMaxDynamicSharedMemorySize, GEMM_SMEM);
    cudaFuncSetAttribute(attn_tc,  cudaFuncAttributeMaxDynamicSharedMemorySize, ATTN_SMEM);

    conv_all<<<XB + 4 * WB, 256>>>((const float4*)x, (const float4*)Wq,
                                   (const float4*)Wk, (const float4*)Wv,
                                   (const float4*)Wo);

    dim3 qkvgrid(DM / 128, MTOT / 128, 3);   // (8, 32, 3)
    gemm_qkv<<<qkvgrid, 256, GEMM_SMEM>>>(xh, bq, bk, bv);

    dim3 agrid(SEQ / 128, NB * NH);          // (16, 32)
    attn_tc<<<agrid, 256, ATTN_SMEM>>>(maskw);

    dim3 ogrid(DM / 128, MTOT / 128);        // (8, 32)
    gemm_o<<<ogrid, 256, GEMM_SMEM>>>(ch, bo, out);
}

// round 17
// speedup vs baseline: 1.0169x; 1.0169x over previous
#include <cuda_runtime.h>
#include <cuda_fp16.h>
#include <math.h>
#include <stdint.h>

#define NH   16
#define HD   64
#define NB   2
#define SEQ  2048
#define DM   1024
#define MTOT (NB*SEQ)

// ---------------- device scratch (allocation-free rule) ----------------
__device__ __align__(256) __half g_Qh[(size_t)NB*NH*SEQ*HD];
__device__ __align__(256) __half g_Kh[(size_t)NB*NH*SEQ*HD];
__device__ __align__(256) __half g_Vh[(size_t)NB*NH*SEQ*HD];
__device__ __align__(256) __half g_xh[(size_t)MTOT*DM];
__device__ __align__(256) __half g_ch[(size_t)MTOT*DM];
__device__ __align__(256) __half g_w4[4][(size_t)DM*DM];   // Wq,Wk,Wv,Wo fp16

// ---------------- helpers ----------------
__device__ __forceinline__ uint32_t smem_u32(const void* p) {
    uint32_t a;
    asm("{ .reg .u64 t; cvta.to.shared.u64 t, %1; cvt.u32.u64 %0, t; }" : "=r"(a) : "l"(p));
    return a;
}
__device__ __forceinline__ uint32_t sw128(uint32_t o) {   // 128B rows
    return o ^ (((o >> 7) & 7u) << 4);
}
__device__ __forceinline__ uint32_t sw64(uint32_t o) {    // 64B rows
    return o ^ (((o >> 7) & 3u) << 4);
}
__device__ __forceinline__ void cpasync16(uint32_t dst, const void* src) {
    asm volatile("cp.async.cg.shared.global [%0], [%1], 16;" :: "r"(dst), "l"(src));
}
__device__ __forceinline__ void cp_commit() {
    asm volatile("cp.async.commit_group;" ::: "memory");
}
__device__ __forceinline__ void cp_wait1() {
    asm volatile("cp.async.wait_group 1;" ::: "memory");
}
__device__ __forceinline__ void cp_wait0() {
    asm volatile("cp.async.wait_group 0;" ::: "memory");
}
__device__ __forceinline__ void ldsm_x4(uint32_t a, uint32_t* r) {
    asm volatile("ldmatrix.sync.aligned.m8n8.x4.shared.b16 {%0,%1,%2,%3}, [%4];"
                 : "=r"(r[0]), "=r"(r[1]), "=r"(r[2]), "=r"(r[3]) : "r"(a));
}
__device__ __forceinline__ void ldsm_x4t(uint32_t a, uint32_t* r) {
    asm volatile("ldmatrix.sync.aligned.m8n8.x4.trans.shared.b16 {%0,%1,%2,%3}, [%4];"
                 : "=r"(r[0]), "=r"(r[1]), "=r"(r[2]), "=r"(r[3]) : "r"(a));
}
__device__ __forceinline__ void mma16816(float* c, const uint32_t* a,
                                         uint32_t b0, uint32_t b1) {
    asm volatile(
        "mma.sync.aligned.m16n8k16.row.col.f32.f16.f16.f32 "
        "{%0,%1,%2,%3}, {%4,%5,%6,%7}, {%8,%9}, {%0,%1,%2,%3};"
        : "+f"(c[0]), "+f"(c[1]), "+f"(c[2]), "+f"(c[3])
        : "r"(a[0]), "r"(a[1]), "r"(a[2]), "r"(a[3]), "r"(b0), "r"(b1));
}
__device__ __forceinline__ float ex2f(float e) {
    float r;
    asm("ex2.approx.f32 %0, %1;" : "=f"(r) : "f"(e));
    return r;
}
__device__ __forceinline__ uint32_t packh(float lo, float hi) {
    __half2 h = __floats2half2_rn(lo, hi);
    return *(uint32_t*)&h;
}

// ---------------- conversions fp32 -> fp16 (x + 4 weights, one launch) ----
#define XB ((int)((size_t)MTOT * DM / 4 / 256))   // 4096
#define WB ((int)((size_t)DM * DM / 4 / 256))     // 1024
__global__ __launch_bounds__(256) void conv_all(const float4* __restrict__ x,
                                                const float4* __restrict__ w0,
                                                const float4* __restrict__ w1,
                                                const float4* __restrict__ w2,
                                                const float4* __restrict__ w3) {
    int blk = blockIdx.x;
    const float4* src;
    __half2* dst;
    int i;
    if (blk < XB) {
        src = x; dst = (__half2*)g_xh;
        i = blk * 256 + threadIdx.x;
    } else {
        blk -= XB;
        const int s = blk / WB;
        src = (s == 0) ? w0 : (s == 1) ? w1 : (s == 2) ? w2 : w3;
        dst = (__half2*)g_w4[s];
        i = (blk - s * WB) * 256 + threadIdx.x;
    }
    float4 v = src[i];
    dst[2*i]   = __floats2half2_rn(v.x, v.y);
    dst[2*i+1] = __floats2half2_rn(v.z, v.w);
}

// ---------------- shared GEMM mainloop (CTA 128x128, BK=32, 3-stage) ------
#define GSTG 16384   // stage stride: A 8K + B 8K

struct GemmCore {
    uint32_t sb;
    int tid, wid, lid, wm, wn, bm, bn;
    float acc[2][8][4];

    __device__ __forceinline__ void init(uint32_t sb_, int bm_, int bn_) {
        sb = sb_; tid = threadIdx.x; wid = tid >> 5; lid = tid & 31;
        wm = wid & 3; wn = wid >> 2; bm = bm_; bn = bn_;
        #pragma unroll
        for (int mi = 0; mi < 2; mi++)
            #pragma unroll
            for (int ni = 0; ni < 8; ni++)
                #pragma unroll
                for (int e = 0; e < 4; e++) acc[mi][ni][e] = 0.f;
    }
    __device__ __forceinline__ void load_stage(const __half* A_, const __half* B_,
                                               int c) {
        const uint32_t base = sb + (uint32_t)(c % 3) * GSTG;
        #pragma unroll
        for (int p = 0; p < 2; p++) {
            const int id = tid + p * 256;
            const int row = id >> 2, ch = id & 3;
            const uint32_t so = sw64((uint32_t)(row * 64 + ch * 16));
            const size_t ga = (size_t)(bm + row) * (DM / 8) + c * 4 + ch;
            const size_t gb = (size_t)(bn + row) * (DM / 8) + c * 4 + ch;
            cpasync16(base + so,        (const uint4*)A_ + ga);
            cpasync16(base + 8192 + so, (const uint4*)B_ + gb);
        }
        cp_commit();
    }
    __device__ __forceinline__ void mainloop(const __half* A_, const __half* B_) {
        const int NIT = DM / 32;
        load_stage(A_, B_, 0);
        load_stage(A_, B_, 1);
        for (int c = 0; c < NIT; c++) {
            if (c == NIT - 1) cp_wait0(); else cp_wait1();
            __syncthreads();
            const uint32_t base = sb + (uint32_t)(c % 3) * GSTG;
            #pragma unroll
            for (int ks = 0; ks < 2; ks++) {
                uint32_t ah[2][4];
                #pragma unroll
                for (int mi = 0; mi < 2; mi++) {
                    const int row = wm * 32 + mi * 16 + (lid & 15);
                    const int colb = (ks * 16 + (lid >> 4) * 8) * 2;
                    ldsm_x4(base + sw64((uint32_t)(row * 64 + colb)), ah[mi]);
                }
                uint32_t bh[8][2];
                #pragma unroll
                for (int nj = 0; nj < 4; nj++) {
                    const int row = wn * 64 + nj * 16 + ((lid >> 4) << 3) + (lid & 7);
                    const int colb = (ks * 16 + ((lid >> 3) & 1) * 8) * 2;
                    uint32_t t[4];
                    ldsm_x4(base + 8192 + sw64((uint32_t)(row * 64 + colb)), t);
                    bh[nj*2][0] = t[0]; bh[nj*2][1] = t[1];
                    bh[nj*2+1][0] = t[2]; bh[nj*2+1][1] = t[3];
                }
                #pragma unroll
                for (int mi = 0; mi < 2; mi++)
                    #pragma unroll
                    for (int ni = 0; ni < 8; ni++)
                        mma16816(acc[mi][ni], ah[mi], bh[ni][0], bh[ni][1]);
            }
            if (c + 2 < NIT) load_stage(A_, B_, c + 2);
        }
    }
};

// QKV fused: z = 0/1/2 -> Q/K/V, half out [b,h,s,d]. Q pre-scaled.
__global__ __launch_bounds__(256, 2)
void gemm_qkv(const __half* __restrict__ A_,
              const float* __restrict__ bq, const float* __restrict__ bk,
              const float* __restrict__ bv)
{
    extern __shared__ char smb[];
    const int z = blockIdx.z;
    const __half* B_ = g_w4[z];
    const float* bias = (z == 0) ? bq : (z == 1) ? bk : bv;
    __half* OutH = (z == 0) ? g_Qh : (z == 1) ? g_Kh : g_Vh;
    const float scl = (z == 0) ? 0.180336880111f : 1.0f;   // 0.125 * log2(e)

    GemmCore g;
    g.init(smem_u32(smb), blockIdx.y * 128, blockIdx.x * 128);
    g.mainloop(A_, B_);

    const int qr = g.lid >> 2, qc = g.lid & 3;
    #pragma unroll
    for (int mi = 0; mi < 2; mi++) {
        #pragma unroll
        for (int half = 0; half < 2; half++) {
            const int m = g.bm + g.wm * 32 + mi * 16 + half * 8 + qr;
            const int n0 = g.bn + g.wn * 64;
            const int b = m >> 11, s = m & (SEQ - 1);
            const int h = n0 >> 6;
            const size_t base = ((size_t)(b * NH + h) * SEQ + s) * HD;
            #pragma unroll
            for (int ni = 0; ni < 8; ni++) {
                const int nloc = ni * 8 + qc * 2;
                const int ng = n0 + nloc;
                *(__half2*)(OutH + base + nloc) = __floats2half2_rn(
                    (g.acc[mi][ni][half*2+0] + bias[ng]) * scl,
                    (g.acc[mi][ni][half*2+1] + bias[ng + 1]) * scl);
            }
        }
    }
}

// Output GEMM: fp32 row-major into d_out  (clock canary: ~29 us at full clock)
__global__ __launch_bounds__(256, 2)
void gemm_o(const __half* __restrict__ A_, const float* __restrict__ bias,
            float* __restrict__ Out)
{
    extern __shared__ char smb[];
    GemmCore g;
    g.init(smem_u32(smb), blockIdx.y * 128, blockIdx.x * 128);
    g.mainloop(A_, g_w4[3]);

    const int qr = g.lid >> 2, qc = g.lid & 3;
    #pragma unroll
    for (int mi = 0; mi < 2; mi++) {
        #pragma unroll
        for (int half = 0; half < 2; half++) {
            const int m = g.bm + g.wm * 32 + mi * 16 + half * 8 + qr;
            const int n0 = g.bn + g.wn * 64;
            float* dst = Out + (size_t)m * DM;
            #pragma unroll
            for (int ni = 0; ni < 8; ni++) {
                const int ng = n0 + ni * 8 + qc * 2;
                float2 o;
                o.x = g.acc[mi][ni][half*2+0] + bias[ng];
                o.y = g.acc[mi][ni][half*2+1] + bias[ng + 1];
                *(float2*)(dst + ng) = o;
            }
        }
    }
}

// ---------------- fp16 tensor-core flash attention (R15 schedule + fused
// softmax/PV per kc-chunk for pipe mixing) --------------------------------
#define MSTRIDE 272                       // 64 words + 16B pad
#define AMOFF   16384                     // mask offset within stage
#define ASTG    (16384 + 128*MSTRIDE)     // 51200
__global__ __launch_bounds__(256, 2) void attn_tc(const uint32_t* __restrict__ maskw)
{
    extern __shared__ char smb[];
    const uint32_t sb = smem_u32(smb);
    const int tid = threadIdx.x, w = tid >> 5, lane = tid & 31;
    const int bh = blockIdx.y, q0 = blockIdx.x * 128;
    const int r = lane >> 2, qc2 = (lane & 3) * 2;
    const int NT = SEQ / 64;
    const uint32_t ONES = 0x3C003C00u;   // half2 {1, 1}

    // ---- stage Q tile, pull fragments ----
    {
        const __half* Q = g_Qh + ((size_t)bh * SEQ + q0) * HD;
        const int row = tid >> 1, cg = (tid & 1) * 4;
        #pragma unroll
        for (int c = 0; c < 4; c++) {
            const uint32_t off = sw128((uint32_t)(row * 128 + (cg + c) * 16));
            *(uint4*)(smb + off) = ((const uint4*)(Q + row * HD))[cg + c];
        }
    }
    __syncthreads();
    uint32_t qh[4][4];
    {
        const int row = w * 16 + ((lane >> 3) & 1) * 8 + (lane & 7);
        #pragma unroll
        for (int kc = 0; kc < 4; kc++) {
            const int chunk = kc * 2 + (lane >> 4);
            ldsm_x4(sb + sw128((uint32_t)(row * 128 + chunk * 16)), qh[kc]);
        }
    }
    __syncthreads();

    float ctx[8][4];
    #pragma unroll
    for (int j = 0; j < 8; j++)
        #pragma unroll
        for (int e = 0; e < 4; e++) ctx[j][e] = 0.f;
    float lacc[4] = {0.f, 0.f, 0.f, 0.f};   // row sums via ones-MMA

    const __half* Kp = g_Kh + (size_t)bh * SEQ * HD;
    const __half* Vp = g_Vh + (size_t)bh * SEQ * HD;
    const uint32_t* Mbase = maskw + ((size_t)bh * SEQ + q0) * SEQ;

    // group 1: K tile only (8 KB); all 256 threads, 2 chunks each
    auto load_K = [&](int kt) {
        const uint32_t stg = sb + (uint32_t)(kt & 1) * ASTG;
        const int row = tid >> 2, cg = (tid & 3) * 2;
        const __half* src = Kp + ((size_t)(kt * 64 + row)) * HD;
        #pragma unroll
        for (int c = 0; c < 2; c++) {
            cpasync16(stg + sw128((uint32_t)(row * 128 + (cg + c) * 16)),
                      (const uint4*)src + cg + c);
        }
        cp_commit();
    };
    // group 2: V tile (8 KB) + mask slab (32 KB)
    auto load_VM = [&](int kt) {
        const uint32_t stg = sb + (uint32_t)(kt & 1) * ASTG;
        {
            const int row = tid >> 2, cg = (tid & 3) * 2;
            const __half* src = Vp + ((size_t)(kt * 64 + row)) * HD;
            #pragma unroll
            for (int c = 0; c < 2; c++) {
                cpasync16(stg + 8192 + sw128((uint32_t)(row * 128 + (cg + c) * 16)),
                          (const uint4*)src + cg + c);
            }
        }
        #pragma unroll
        for (int i = 0; i < 8; i++) {
            const int id = i * 256 + tid;
            const int row = id >> 4, ch = id & 15;
            cpasync16(stg + AMOFF + (uint32_t)(row * MSTRIDE + ch * 16),
                      Mbase + (size_t)row * SEQ + kt * 64 + ch * 4);
        }
        cp_commit();
    };

    load_K(0);
    load_VM(0);

    for (int kt = 0; kt < NT; kt++) {
        // pending at top: [K(kt), VM(kt)] -> wait<=1 releases K(kt)
        cp_wait1();
        __syncthreads();
        if (kt + 1 < NT) load_K(kt + 1);
        const uint32_t base = sb + (uint32_t)(kt & 1) * ASTG;

        // ---- S = Q K^T (V + mask of this tile still in flight) ----
        float sacc[8][4];
        #pragma unroll
        for (int j = 0; j < 8; j++) {
            #pragma unroll
            for (int e = 0; e < 4; e++) sacc[j][e] = 0.f;
            uint32_t kb[8];
            #pragma unroll
            for (int half = 0; half < 2; half++) {
                const int row = j * 8 + (lane & 7);
                const int chunk = half * 4 + (lane >> 3);
                ldsm_x4(base + sw128((uint32_t)(row * 128 + chunk * 16)), kb + half * 4);
            }
            #pragma unroll
            for (int kc = 0; kc < 4; kc++) {
                const int i0 = (kc >> 1) * 4 + (kc & 1) * 2;
                mma16816(sacc[j], qh[kc], kb[i0], kb[i0 + 1]);
            }
        }

        // pending: [VM(kt), K(kt+1)] -> wait<=1 releases VM(kt)
        if (kt + 1 < NT) cp_wait1(); else cp_wait0();
        __syncthreads();
        if (kt + 1 < NT) load_VM(kt + 1);

        // ---- fused per-kc: softmax (MUFU/ALU/LDS) interleaved with PV MMAs ----
        const char* mrow0 = smb + (kt & 1) * ASTG + AMOFF + (w * 16 + r) * MSTRIDE;
        const char* mrow1 = mrow0 + 8 * MSTRIDE;
        #pragma unroll
        for (int kc = 0; kc < 4; kc++) {
            uint32_t pf[4];
            #pragma unroll
            for (int jj = 0; jj < 2; jj++) {
                const int j = kc * 2 + jj;
                uint2 m0 = *(const uint2*)(mrow0 + (j * 8 + qc2) * 4);
                uint2 m1 = *(const uint2*)(mrow1 + (j * 8 + qc2) * 4);
                float p0 = m0.x ? ex2f(sacc[j][0]) : 0.f;
                float p1 = m0.y ? ex2f(sacc[j][1]) : 0.f;
                float p2 = m1.x ? ex2f(sacc[j][2]) : 0.f;
                float p3 = m1.y ? ex2f(sacc[j][3]) : 0.f;
                pf[jj * 2 + 0] = packh(p0, p1);
                pf[jj * 2 + 1] = packh(p2, p3);
            }
            mma16816(lacc, pf, ONES, ONES);
            #pragma unroll
            for (int dp = 0; dp < 4; dp++) {
                const int row = kc * 16 + ((lane >> 3) & 1) * 8 + (lane & 7);
                const int chunk = dp * 2 + (lane >> 4);
                uint32_t vb[4];
                ldsm_x4t(base + 8192 + sw128((uint32_t)(row * 128 + chunk * 16)), vb);
                mma16816(ctx[dp*2],   pf, vb[0], vb[1]);
                mma16816(ctx[dp*2+1], pf, vb[2], vb[3]);
            }
        }
    }

    // ---- normalize + write ctx (fp16) into [b, s, h*64+d] ----
    const float inv0 = (lacc[0] > 0.f) ? 1.f / lacc[0] : 0.f;
    const float inv1 = (lacc[2] > 0.f) ? 1.f / lacc[2] : 0.f;
    const int b = bh >> 4, h = bh & (NH - 1);
    const int s0 = q0 + w * 16 + r;
    const size_t base0 = ((size_t)b * SEQ + s0) * DM + h * 64;
    const size_t base1 = base0 + (size_t)8 * DM;
    #pragma unroll
    for (int j = 0; j < 8; j++) {
        const int d = j * 8 + qc2;
        *(__half2*)(g_ch + base0 + d) =
            __floats2half2_rn(ctx[j][0] * inv0, ctx[j][1] * inv0);
        *(__half2*)(g_ch + base1 + d) =
            __floats2half2_rn(ctx[j][2] * inv1, ctx[j][3] * inv1);
    }
}

// ---------------- launch ----------------
extern "C" void kernel_launch(void* const* d_in, const int* in_sizes, int n_in,
                              void* d_out, int out_size)
{
    const float* x  = (const float*)d_in[0];
    const uint32_t* maskw = (const uint32_t*)d_in[1];
    const float* Wq = (const float*)d_in[2];
    const float* bq = (const float*)d_in[3];
    const float* Wk = (const float*)d_in[4];
    const float* bk = (const float*)d_in[5];
    const float* Wv = (const float*)d_in[6];
    const float* bv = (const float*)d_in[7];
    const float* Wo = (const float*)d_in[8];
    const float* bo = (const float*)d_in[9];
    float* out = (float*)d_out;

    __half *xh, *ch;
    cudaGetSymbolAddress((void**)&xh, g_xh);
    cudaGetSymbolAddress((void**)&ch, g_ch);

    const int GEMM_SMEM = 3 * GSTG;   // 49152
    const int ATTN_SMEM = 2 * ASTG;   // 102400
    cudaFuncSetAttribute(gemm_qkv, cudaFuncAttributeMaxDynamicSharedMemorySize, GEMM_SMEM);
    cudaFuncSetAttribute(gemm_o,   cudaFuncAttributeMaxDynamicSharedMemorySize, GEMM_SMEM);
    cudaFuncSetAttribute(attn_tc,  cudaFuncAttributeMaxDynamicSharedMemorySize, ATTN_SMEM);

    conv_all<<<XB + 4 * WB, 256>>>((const float4*)x, (const float4*)Wq,
                                   (const float4*)Wk, (const float4*)Wv,
                                   (const float4*)Wo);

    dim3 qkvgrid(DM / 128, MTOT / 128, 3);   // (8, 32, 3)
    gemm_qkv<<<qkvgrid, 256, GEMM_SMEM>>>(xh, bq, bk, bv);

    dim3 agrid(SEQ / 128, NB * NH);          // (16, 32)
    attn_tc<<<agrid, 256, ATTN_SMEM>>>(maskw);

    dim3 ogrid(DM / 128, MTOT / 128);        // (8, 32)
    gemm_o<<<ogrid, 256, GEMM_SMEM>>>(ch, bo, out);
}